// round 1
// baseline (speedup 1.0000x reference)
#include <cuda_runtime.h>
#include <cuda_bf16.h>
#include <math.h>

// ---------------- problem constants ----------------
#define BB   16
#define CC   256
#define HH   32
#define WWI  32
#define HWSZ 1024          // H*W
#define DH   32
#define HEADS 8
#define WSZ  4
#define KTOP 4
#define MRC  1024          // MR*C
#define NWIN 64
#define WS   16
#define EPSV 1e-5f

// ---------------- device scratch ----------------
__device__ float g_h0 [BB * CC  * HWSZ];   // gelu(bn0(x))
__device__ float g_qkv[BB * 3*CC * HWSZ];  // qkv projection
__device__ float g_qm [BB * HEADS * NWIN * DH];
__device__ float g_km [BB * HEADS * NWIN * DH];
__device__ int   g_idx[BB * HEADS * NWIN * KTOP];
__device__ float g_msg[BB * CC  * HWSZ];   // attention output (unwindowed)
__device__ float g_x1 [BB * CC  * HWSZ];   // x + merge
__device__ float g_h1 [BB * MRC * HWSZ];   // gelu(bn1(w1@x1))
__device__ float g_h2 [BB * MRC * HWSZ];   // gelu(bn2(dwconv(h1)))

__device__ __forceinline__ float gelu_f(float x) {
    return 0.5f * x * (1.0f + erff(x * 0.7071067811865475f));
}

// ---------------- kernel 1: h0 = gelu(bn0(x)) ----------------
__global__ void bn0_gelu_k(const float* __restrict__ x,
                           const float* __restrict__ g, const float* __restrict__ b,
                           const float* __restrict__ m, const float* __restrict__ v) {
    int i = blockIdx.x * 256 + threadIdx.x;
    if (i >= BB * CC * HWSZ) return;
    int c = (i >> 10) & (CC - 1);
    float s = g[c] * rsqrtf(v[c] + EPSV);
    g_h0[i] = gelu_f((x[i] - m[c]) * s + b[c]);
}

// ---------------- generic fused GEMM ----------------
// Out[b,o,n] = epilogue( sum_c Wm[o,c] * A[b,c,n] )
// MODE 0: plain
// MODE 1: Res + acc + bias[o]
// MODE 2: gelu(bn(acc))
// MODE 3: Res + bn(acc)
template<int MODE>
__global__ void gemm_k(const float* __restrict__ Wm,
                       const float* __restrict__ A,
                       float* __restrict__ Out,
                       int O, int Kd,
                       const float* __restrict__ Res,
                       const float* __restrict__ bias,
                       const float* __restrict__ g,  const float* __restrict__ bb,
                       const float* __restrict__ mm, const float* __restrict__ vv) {
    __shared__ float Ws[16][65];
    __shared__ float As[16][65];
    int b   = blockIdx.z;
    int om  = blockIdx.x * 64;
    int n0  = blockIdx.y * 64;
    int tid = threadIdx.x;
    int ty = tid >> 4, tx = tid & 15;
    float acc[4][4] = {};
    const float* Ab = A + (size_t)b * Kd * HWSZ;

    for (int k0 = 0; k0 < Kd; k0 += 16) {
        #pragma unroll
        for (int e = tid; e < 1024; e += 256) {
            int r = e >> 4, c = e & 15;
            Ws[c][r] = Wm[(size_t)(om + r) * Kd + k0 + c];
        }
        #pragma unroll
        for (int e = tid; e < 1024; e += 256) {
            int kk = e >> 6, nc = e & 63;
            As[kk][nc] = Ab[(size_t)(k0 + kk) * HWSZ + n0 + nc];
        }
        __syncthreads();
        #pragma unroll
        for (int kk = 0; kk < 16; kk++) {
            float av[4], bv[4];
            #pragma unroll
            for (int i = 0; i < 4; i++) av[i] = Ws[kk][ty * 4 + i];
            #pragma unroll
            for (int j = 0; j < 4; j++) bv[j] = As[kk][tx * 4 + j];
            #pragma unroll
            for (int i = 0; i < 4; i++)
                #pragma unroll
                for (int j = 0; j < 4; j++)
                    acc[i][j] = fmaf(av[i], bv[j], acc[i][j]);
        }
        __syncthreads();
    }

    #pragma unroll
    for (int i = 0; i < 4; i++) {
        int o = om + ty * 4 + i;
        float s = 0.f, bshift = 0.f;
        if (MODE == 2 || MODE == 3) {
            s = g[o] * rsqrtf(vv[o] + EPSV);
            bshift = bb[o] - mm[o] * s;
        }
        #pragma unroll
        for (int j = 0; j < 4; j++) {
            int n = n0 + tx * 4 + j;
            size_t oi = (size_t)b * O * HWSZ + (size_t)o * HWSZ + n;
            float r = acc[i][j];
            if (MODE == 1) r = Res[oi] + r + bias[o];
            if (MODE == 2) r = gelu_f(r * s + bshift);
            if (MODE == 3) r = Res[oi] + (r * s + bshift);
            Out[oi] = r;
        }
    }
}

// ---------------- window means of q and k ----------------
__global__ void wmean_k() {
    int i = blockIdx.x * 256 + threadIdx.x;   // over B*HEADS*NWIN*DH
    if (i >= BB * HEADS * NWIN * DH) return;
    int d = i & 31;
    int n = (i >> 5) & 63;
    int h = (i >> 11) & 7;
    int b = i >> 14;
    int wy = n >> 3, wx = n & 7;
    const float* qb = g_qkv + ((size_t)b * 3 * CC + h * DH + d) * HWSZ;
    const float* kb = qb + (size_t)CC * HWSZ;
    float sq = 0.f, sk = 0.f;
    #pragma unroll
    for (int t = 0; t < 16; t++) {
        int hw = ((wy * 4 + (t >> 2)) << 5) + wx * 4 + (t & 3);
        sq += qb[hw];
        sk += kb[hw];
    }
    g_qm[i] = sq * 0.0625f;
    g_km[i] = sk * 0.0625f;
}

// ---------------- window affinity + exact top-4 ----------------
__global__ void topk_k() {
    // block = 128 threads = 4 warps, each warp = one (b,h,i) row
    int row  = blockIdx.x * 4 + (threadIdx.x >> 5);  // b*512 + h*64 + i
    int lane = threadIdx.x & 31;
    int wi   = threadIdx.x >> 5;
    __shared__ float qsh[4][32];
    __shared__ float ssh[4][64];
    int h = (row >> 6) & 7;
    int b = row >> 9;
    qsh[wi][lane] = g_qm[(size_t)row * 32 + lane];
    __syncwarp();
    const float* kmb = g_km + ((size_t)(b * HEADS + h) * NWIN) * DH;
    float s0 = 0.f, s1 = 0.f;
    #pragma unroll
    for (int d = 0; d < 32; d++) {
        float q = qsh[wi][d];
        s0 += q * kmb[lane * 32 + d];
        s1 += q * kmb[(lane + 32) * 32 + d];
    }
    ssh[wi][lane]      = s0;
    ssh[wi][lane + 32] = s1;
    __syncwarp();
    if (lane == 0) {
        int taken[KTOP];
        for (int t = 0; t < KTOP; t++) {
            float best = -INFINITY; int bj = -1;
            for (int j = 0; j < 64; j++) {
                bool used = false;
                for (int u = 0; u < t; u++) if (taken[u] == j) used = true;
                if (!used && ssh[wi][j] > best) { best = ssh[wi][j]; bj = j; }
            }
            taken[t] = bj;
            g_idx[(size_t)row * KTOP + t] = bj;
        }
    }
}

// ---------------- gathered window attention ----------------
__global__ void attn_k() {
    int bid = blockIdx.x;            // b*512 + h*64 + n
    int n = bid & 63;
    int h = (bid >> 6) & 7;
    int b = bid >> 9;
    __shared__ float qs[16][33];
    __shared__ float ks[64][33];
    __shared__ float vs[64][33];
    __shared__ float sc[16][64];
    __shared__ int   widx[KTOP];
    int tid = threadIdx.x;           // 128 threads
    if (tid < KTOP) widx[tid] = g_idx[(size_t)bid * KTOP + tid];
    __syncthreads();

    int wy = n >> 3, wx = n & 7;
    const float* qbase = g_qkv + ((size_t)b * 3 * CC + h * DH) * HWSZ;
    const float* kbase = qbase + (size_t)CC * HWSZ;
    const float* vbase = qbase + (size_t)2 * CC * HWSZ;

    // load q: 512 elements, e -> (d = e>>4, t = e&15)
    for (int e = tid; e < 512; e += 128) {
        int d = e >> 4, t = e & 15;
        int hw = ((wy * 4 + (t >> 2)) << 5) + wx * 4 + (t & 3);
        qs[t][d] = qbase[(size_t)d * HWSZ + hw];
    }
    // load gathered k/v: 2048 elements, e -> (d = e>>6, kt = e&63)
    for (int e = tid; e < 2048; e += 128) {
        int d = e >> 6, kt = e & 63;
        int j = widx[kt >> 4];
        int t = kt & 15;
        int jy = j >> 3, jx = j & 7;
        int hw = ((jy * 4 + (t >> 2)) << 5) + jx * 4 + (t & 3);
        ks[kt][d] = kbase[(size_t)d * HWSZ + hw];
        vs[kt][d] = vbase[(size_t)d * HWSZ + hw];
    }
    __syncthreads();

    int warp = tid >> 5, lane = tid & 31;
    const float scale = 0.17677669529663687f;   // 1/sqrt(32)
    #pragma unroll
    for (int rr = 0; rr < 4; rr++) {
        int row = warp * 4 + rr;
        float s0 = 0.f, s1 = 0.f;
        #pragma unroll
        for (int d = 0; d < 32; d++) {
            float qv = qs[row][d];
            s0 += qv * ks[lane][d];
            s1 += qv * ks[lane + 32][d];
        }
        s0 *= scale; s1 *= scale;
        float mx = fmaxf(s0, s1);
        #pragma unroll
        for (int off = 16; off; off >>= 1) mx = fmaxf(mx, __shfl_xor_sync(0xffffffffu, mx, off));
        float e0 = expf(s0 - mx), e1 = expf(s1 - mx);
        float sum = e0 + e1;
        #pragma unroll
        for (int off = 16; off; off >>= 1) sum += __shfl_xor_sync(0xffffffffu, sum, off);
        float inv = 1.0f / sum;
        sc[row][lane]      = e0 * inv;
        sc[row][lane + 32] = e1 * inv;
    }
    __syncwarp();
    float* mbase = g_msg + ((size_t)b * CC + h * DH) * HWSZ;
    #pragma unroll
    for (int rr = 0; rr < 4; rr++) {
        int row = warp * 4 + rr;   // token t
        float acc = 0.f;
        #pragma unroll
        for (int k = 0; k < 64; k++) acc += sc[row][k] * vs[k][lane];
        int hw = ((wy * 4 + (row >> 2)) << 5) + wx * 4 + (row & 3);
        mbase[(size_t)lane * HWSZ + hw] = acc;
    }
}

// ---------------- depthwise 3x3 + bn2 + gelu ----------------
__global__ void dw_k(const float* __restrict__ dw,
                     const float* __restrict__ g2, const float* __restrict__ b2,
                     const float* __restrict__ m2, const float* __restrict__ v2) {
    int i = blockIdx.x * 256 + threadIdx.x;     // B*1024*32*32
    if (i >= BB * MRC * HWSZ) return;
    int xw = i & 31;
    int yh = (i >> 5) & 31;
    int c  = (i >> 10) & (MRC - 1);
    int b  = i >> 20;
    const float* p = g_h1 + ((size_t)b * MRC + c) * HWSZ;
    const float* w = dw + c * 9;
    float acc = 0.f;
    #pragma unroll
    for (int dy = -1; dy <= 1; dy++) {
        int y = yh + dy;
        if (y < 0 || y > 31) continue;
        #pragma unroll
        for (int dx = -1; dx <= 1; dx++) {
            int x = xw + dx;
            if (x < 0 || x > 31) continue;
            acc += w[(dy + 1) * 3 + (dx + 1)] * p[y * 32 + x];
        }
    }
    float s = g2[c] * rsqrtf(v2[c] + EPSV);
    g_h2[i] = gelu_f((acc - m2[c]) * s + b2[c]);
}

// ---------------- launcher ----------------
extern "C" void kernel_launch(void* const* d_in, const int* in_sizes, int n_in,
                              void* d_out, int out_size) {
    const float* x      = (const float*)d_in[0];
    const float* bn0_g  = (const float*)d_in[1];
    const float* bn0_b  = (const float*)d_in[2];
    const float* bn0_m  = (const float*)d_in[3];
    const float* bn0_v  = (const float*)d_in[4];
    const float* w_qkv  = (const float*)d_in[5];
    const float* w_mrg  = (const float*)d_in[6];
    const float* b_mrg  = (const float*)d_in[7];
    const float* w1     = (const float*)d_in[8];
    const float* bn1_g  = (const float*)d_in[9];
    const float* bn1_b  = (const float*)d_in[10];
    const float* bn1_m  = (const float*)d_in[11];
    const float* bn1_v  = (const float*)d_in[12];
    const float* dw     = (const float*)d_in[13];
    const float* bn2_g  = (const float*)d_in[14];
    const float* bn2_b  = (const float*)d_in[15];
    const float* bn2_m  = (const float*)d_in[16];
    const float* bn2_v  = (const float*)d_in[17];
    const float* w2     = (const float*)d_in[18];
    const float* bn3_g  = (const float*)d_in[19];
    const float* bn3_b  = (const float*)d_in[20];
    const float* bn3_m  = (const float*)d_in[21];
    const float* bn3_v  = (const float*)d_in[22];

    float *h0, *qkv, *msg, *x1, *h1, *h2;
    cudaGetSymbolAddress((void**)&h0,  g_h0);
    cudaGetSymbolAddress((void**)&qkv, g_qkv);
    cudaGetSymbolAddress((void**)&msg, g_msg);
    cudaGetSymbolAddress((void**)&x1,  g_x1);
    cudaGetSymbolAddress((void**)&h1,  g_h1);
    cudaGetSymbolAddress((void**)&h2,  g_h2);

    // 1. h0 = gelu(bn0(x))
    bn0_gelu_k<<<(BB * CC * HWSZ + 255) / 256, 256>>>(x, bn0_g, bn0_b, bn0_m, bn0_v);

    // 2. qkv = w_qkv @ h0
    gemm_k<0><<<dim3(768 / 64, HWSZ / 64, BB), 256>>>(
        w_qkv, h0, qkv, 768, 256, nullptr, nullptr, nullptr, nullptr, nullptr, nullptr);

    // 3. window means
    wmean_k<<<(BB * HEADS * NWIN * DH + 255) / 256, 256>>>();

    // 4. affinity + top-4
    topk_k<<<BB * HEADS * NWIN / 4, 128>>>();

    // 5. gathered attention -> msg (unwindowed layout)
    attn_k<<<BB * HEADS * NWIN, 128>>>();

    // 6. x1 = x + w_merge @ msg + b_merge
    gemm_k<1><<<dim3(CC / 64, HWSZ / 64, BB), 256>>>(
        w_mrg, msg, x1, CC, 256, x, b_mrg, nullptr, nullptr, nullptr, nullptr);

    // 7. h1 = gelu(bn1(w1 @ x1))
    gemm_k<2><<<dim3(MRC / 64, HWSZ / 64, BB), 256>>>(
        w1, x1, h1, MRC, 256, nullptr, nullptr, bn1_g, bn1_b, bn1_m, bn1_v);

    // 8. h2 = gelu(bn2(dwconv3x3(h1)))
    dw_k<<<(BB * MRC * HWSZ + 255) / 256, 256>>>(dw, bn2_g, bn2_b, bn2_m, bn2_v);

    // 9. out = x1 + bn3(w2 @ h2)
    gemm_k<3><<<dim3(CC / 64, HWSZ / 64, BB), 256>>>(
        w2, h2, (float*)d_out, CC, 1024, x1, nullptr, bn3_g, bn3_b, bn3_m, bn3_v);
}

// round 3
// speedup vs baseline: 2.2583x; 2.2583x over previous
#include <cuda_runtime.h>
#include <cuda_bf16.h>
#include <cstdint>
#include <math.h>

// ---------------- problem constants ----------------
#define BB   16
#define CC   256
#define HWSZ 1024
#define DH   32
#define HEADS 8
#define KTOP 4
#define MRC  1024
#define NWIN 64
#define EPSV 1e-5f

// ---------------- device scratch ----------------
__device__ float g_h0 [BB * CC  * HWSZ];
__device__ float g_qkv[BB * 3*CC * HWSZ];
__device__ float g_qm [BB * HEADS * NWIN * DH];
__device__ float g_km [BB * HEADS * NWIN * DH];
__device__ int   g_idx[BB * HEADS * NWIN * KTOP];
__device__ float g_msg[BB * CC  * HWSZ];
__device__ float g_x1 [BB * CC  * HWSZ];
__device__ float g_h1 [BB * MRC * HWSZ];
__device__ float g_h2 [BB * MRC * HWSZ];

__device__ __forceinline__ float gelu_f(float x) {
    return 0.5f * x * (1.0f + erff(x * 0.7071067811865475f));
}

// ---------------- bf16 warp MMA ----------------
__device__ __forceinline__ void mma_bf16(float* d, const uint32_t* a, uint32_t b0, uint32_t b1) {
    asm volatile(
        "mma.sync.aligned.m16n8k16.row.col.f32.bf16.bf16.f32 "
        "{%0,%1,%2,%3}, {%4,%5,%6,%7}, {%8,%9}, {%0,%1,%2,%3};"
        : "+f"(d[0]), "+f"(d[1]), "+f"(d[2]), "+f"(d[3])
        : "r"(a[0]), "r"(a[1]), "r"(a[2]), "r"(a[3]), "r"(b0), "r"(b1));
}

__device__ __forceinline__ void cvt_split(float x, __nv_bfloat16& h, __nv_bfloat16& l) {
    h = __float2bfloat16(x);
    l = __float2bfloat16(x - __bfloat162float(h));
}

// smem layout constants (per stage, bytes)
#define WS_STRIDE 40          // bf16 elems per W row (32 used + pad)
#define AS_STRIDE 34          // bf16 elems per A row (32 used + pad)
#define WS_HI_ELEM 0
#define WS_LO_ELEM 5120       // 128*40
#define AS_BYTE_OFF 20480     // 2*128*40*2
#define AS_LO_ELEM 4352       // 128*34
#define STAGE_BYTES 37888
#define GEMM_SMEM (2 * STAGE_BYTES)

// ---------------- kernel: h0 = gelu(bn0(x)) ----------------
__global__ void bn0_gelu_k(const float* __restrict__ x,
                           const float* __restrict__ g, const float* __restrict__ b,
                           const float* __restrict__ m, const float* __restrict__ v) {
    int i = blockIdx.x * 256 + threadIdx.x;
    if (i >= BB * CC * HWSZ) return;
    int c = (i >> 10) & (CC - 1);
    float s = g[c] * rsqrtf(v[c] + EPSV);
    g_h0[i] = gelu_f((x[i] - m[c]) * s + b[c]);
}

// ---------------- tensor-core fused GEMM (bf16 3-term split) ----------------
// Out[b,o,n] = epilogue( sum_c Wm[o,c] * A[b,c,n] )
// CTA: 128(o) x 128(n), 256 threads = 8 warps (4 in M x 2 in N), warp tile 32x64.
template<int MODE>
__global__ void __launch_bounds__(256, 1)
mgemm_k(const float* __restrict__ Wm, const float* __restrict__ A,
        float* __restrict__ Out, int O, int Kd,
        const float* __restrict__ Res, const float* __restrict__ bias,
        const float* __restrict__ g,  const float* __restrict__ bb,
        const float* __restrict__ mm, const float* __restrict__ vv) {
    extern __shared__ char smc[];
    const int tid = threadIdx.x, lane = tid & 31, warp = tid >> 5;
    const int b = blockIdx.z, om = blockIdx.x * 128, n0 = blockIdx.y * 128;
    const int wm = warp >> 1, wn = warp & 1;
    const int gq = lane >> 2, tq = lane & 3;

    const float* Wb = Wm + (size_t)om * Kd;
    const float* Ab = A + (size_t)b * Kd * HWSZ + n0;

    float acc[2][8][4];
    #pragma unroll
    for (int mt = 0; mt < 2; mt++)
        #pragma unroll
        for (int nt = 0; nt < 8; nt++)
            #pragma unroll
            for (int r = 0; r < 4; r++) acc[mt][nt][r] = 0.f;

    const int wrow = tid >> 3;        // 0..31
    const int wcol = (tid & 7) * 4;   // 0,4,..28
    const int acr  = tid >> 5;        // 0..7
    const int acn  = (tid & 31) * 4;  // 0..124

    float4 wv[4], av[4];
    const int nch = Kd >> 5;

    // ---- load chunk 0 ----
    #pragma unroll
    for (int it = 0; it < 4; it++)
        wv[it] = *(const float4*)(Wb + (size_t)(it * 32 + wrow) * Kd + wcol);
    #pragma unroll
    for (int it = 0; it < 4; it++)
        av[it] = *(const float4*)(Ab + (size_t)(it * 8 + acr) * HWSZ + acn);

    // ---- store chunk 0 into stage 0 ----
    {
        __nv_bfloat16* ws_hi = (__nv_bfloat16*)smc;
        __nv_bfloat16* ws_lo = ws_hi + WS_LO_ELEM;
        __nv_bfloat16* as_hi = (__nv_bfloat16*)(smc + AS_BYTE_OFF);
        __nv_bfloat16* as_lo = as_hi + AS_LO_ELEM;
        #pragma unroll
        for (int it = 0; it < 4; it++) {
            __nv_bfloat16 h4[4], l4[4];
            cvt_split(wv[it].x, h4[0], l4[0]); cvt_split(wv[it].y, h4[1], l4[1]);
            cvt_split(wv[it].z, h4[2], l4[2]); cvt_split(wv[it].w, h4[3], l4[3]);
            int idx = (it * 32 + wrow) * WS_STRIDE + wcol;
            *(uint2*)&ws_hi[idx] = *(uint2*)h4;
            *(uint2*)&ws_lo[idx] = *(uint2*)l4;
        }
        #pragma unroll
        for (int it = 0; it < 4; it++) {
            __nv_bfloat16 h4[4], l4[4];
            cvt_split(av[it].x, h4[0], l4[0]); cvt_split(av[it].y, h4[1], l4[1]);
            cvt_split(av[it].z, h4[2], l4[2]); cvt_split(av[it].w, h4[3], l4[3]);
            int c = it * 8 + acr;
            #pragma unroll
            for (int j = 0; j < 4; j++) {
                as_hi[(acn + j) * AS_STRIDE + c] = h4[j];
                as_lo[(acn + j) * AS_STRIDE + c] = l4[j];
            }
        }
    }
    __syncthreads();

    for (int ch = 0; ch < nch; ch++) {
        int s = ch & 1;
        char* st = smc + s * STAGE_BYTES;
        int k0n = (ch + 1) << 5;

        if (ch + 1 < nch) {
            #pragma unroll
            for (int it = 0; it < 4; it++)
                wv[it] = *(const float4*)(Wb + (size_t)(it * 32 + wrow) * Kd + k0n + wcol);
            #pragma unroll
            for (int it = 0; it < 4; it++)
                av[it] = *(const float4*)(Ab + (size_t)(k0n + it * 8 + acr) * HWSZ + acn);
        }

        // ---- compute from stage s ----
        const __nv_bfloat16* ws_hi = (const __nv_bfloat16*)st;
        const __nv_bfloat16* ws_lo = ws_hi + WS_LO_ELEM;
        const __nv_bfloat16* as_hi = (const __nv_bfloat16*)(st + AS_BYTE_OFF);
        const __nv_bfloat16* as_lo = as_hi + AS_LO_ELEM;

        #pragma unroll
        for (int ks = 0; ks < 2; ks++) {
            uint32_t afh[2][4], afl[2][4];
            #pragma unroll
            for (int mt = 0; mt < 2; mt++) {
                int rb = wm * 32 + mt * 16;
                int cb = ks * 16 + 2 * tq;
                afh[mt][0] = *(const uint32_t*)&ws_hi[(rb + gq)     * WS_STRIDE + cb];
                afh[mt][1] = *(const uint32_t*)&ws_hi[(rb + gq + 8) * WS_STRIDE + cb];
                afh[mt][2] = *(const uint32_t*)&ws_hi[(rb + gq)     * WS_STRIDE + cb + 8];
                afh[mt][3] = *(const uint32_t*)&ws_hi[(rb + gq + 8) * WS_STRIDE + cb + 8];
                afl[mt][0] = *(const uint32_t*)&ws_lo[(rb + gq)     * WS_STRIDE + cb];
                afl[mt][1] = *(const uint32_t*)&ws_lo[(rb + gq + 8) * WS_STRIDE + cb];
                afl[mt][2] = *(const uint32_t*)&ws_lo[(rb + gq)     * WS_STRIDE + cb + 8];
                afl[mt][3] = *(const uint32_t*)&ws_lo[(rb + gq + 8) * WS_STRIDE + cb + 8];
            }
            #pragma unroll
            for (int nt = 0; nt < 8; nt++) {
                int nb = wn * 64 + nt * 8 + gq;
                int kb = ks * 16 + 2 * tq;
                uint32_t bh0 = *(const uint32_t*)&as_hi[nb * AS_STRIDE + kb];
                uint32_t bh1 = *(const uint32_t*)&as_hi[nb * AS_STRIDE + kb + 8];
                uint32_t bl0 = *(const uint32_t*)&as_lo[nb * AS_STRIDE + kb];
                uint32_t bl1 = *(const uint32_t*)&as_lo[nb * AS_STRIDE + kb + 8];
                #pragma unroll
                for (int mt = 0; mt < 2; mt++) {
                    mma_bf16(acc[mt][nt], afh[mt], bh0, bh1);
                    mma_bf16(acc[mt][nt], afh[mt], bl0, bl1);
                    mma_bf16(acc[mt][nt], afl[mt], bh0, bh1);
                }
            }
        }

        // ---- store next chunk into stage s^1 ----
        if (ch + 1 < nch) {
            char* st2 = smc + (s ^ 1) * STAGE_BYTES;
            __nv_bfloat16* ws_hi2 = (__nv_bfloat16*)st2;
            __nv_bfloat16* ws_lo2 = ws_hi2 + WS_LO_ELEM;
            __nv_bfloat16* as_hi2 = (__nv_bfloat16*)(st2 + AS_BYTE_OFF);
            __nv_bfloat16* as_lo2 = as_hi2 + AS_LO_ELEM;
            #pragma unroll
            for (int it = 0; it < 4; it++) {
                __nv_bfloat16 h4[4], l4[4];
                cvt_split(wv[it].x, h4[0], l4[0]); cvt_split(wv[it].y, h4[1], l4[1]);
                cvt_split(wv[it].z, h4[2], l4[2]); cvt_split(wv[it].w, h4[3], l4[3]);
                int idx = (it * 32 + wrow) * WS_STRIDE + wcol;
                *(uint2*)&ws_hi2[idx] = *(uint2*)h4;
                *(uint2*)&ws_lo2[idx] = *(uint2*)l4;
            }
            #pragma unroll
            for (int it = 0; it < 4; it++) {
                __nv_bfloat16 h4[4], l4[4];
                cvt_split(av[it].x, h4[0], l4[0]); cvt_split(av[it].y, h4[1], l4[1]);
                cvt_split(av[it].z, h4[2], l4[2]); cvt_split(av[it].w, h4[3], l4[3]);
                int c = it * 8 + acr;
                #pragma unroll
                for (int j = 0; j < 4; j++) {
                    as_hi2[(acn + j) * AS_STRIDE + c] = h4[j];
                    as_lo2[(acn + j) * AS_STRIDE + c] = l4[j];
                }
            }
        }
        __syncthreads();
    }

    // ---- epilogue: direct stores ----
    #pragma unroll
    for (int mt = 0; mt < 2; mt++) {
        int o0 = om + wm * 32 + mt * 16 + gq;
        int o1 = o0 + 8;
        float s0 = 0.f, bs0 = 0.f, s1 = 0.f, bs1 = 0.f, bi0 = 0.f, bi1 = 0.f;
        if (MODE == 2 || MODE == 3) {
            s0 = g[o0] * rsqrtf(vv[o0] + EPSV); bs0 = bb[o0] - mm[o0] * s0;
            s1 = g[o1] * rsqrtf(vv[o1] + EPSV); bs1 = bb[o1] - mm[o1] * s1;
        }
        if (MODE == 1) { bi0 = bias[o0]; bi1 = bias[o1]; }
        #pragma unroll
        for (int nt = 0; nt < 8; nt++) {
            int n = n0 + wn * 64 + nt * 8 + 2 * tq;
            size_t oi0 = ((size_t)b * O + o0) * HWSZ + n;
            size_t oi1 = ((size_t)b * O + o1) * HWSZ + n;
            float r0 = acc[mt][nt][0], r1 = acc[mt][nt][1];
            float r2 = acc[mt][nt][2], r3 = acc[mt][nt][3];
            if (MODE == 1) {
                float2 e0 = *(const float2*)&Res[oi0];
                float2 e1 = *(const float2*)&Res[oi1];
                r0 += e0.x + bi0; r1 += e0.y + bi0;
                r2 += e1.x + bi1; r3 += e1.y + bi1;
            }
            if (MODE == 2) {
                r0 = gelu_f(r0 * s0 + bs0); r1 = gelu_f(r1 * s0 + bs0);
                r2 = gelu_f(r2 * s1 + bs1); r3 = gelu_f(r3 * s1 + bs1);
            }
            if (MODE == 3) {
                float2 e0 = *(const float2*)&Res[oi0];
                float2 e1 = *(const float2*)&Res[oi1];
                r0 = e0.x + r0 * s0 + bs0; r1 = e0.y + r1 * s0 + bs0;
                r2 = e1.x + r2 * s1 + bs1; r3 = e1.y + r3 * s1 + bs1;
            }
            float2 v0 = {r0, r1}, v1 = {r2, r3};
            *(float2*)&Out[oi0] = v0;
            *(float2*)&Out[oi1] = v1;
        }
    }
}

// ---------------- window means of q and k ----------------
__global__ void wmean_k() {
    int i = blockIdx.x * 256 + threadIdx.x;
    if (i >= BB * HEADS * NWIN * DH) return;
    int d = i & 31;
    int n = (i >> 5) & 63;
    int h = (i >> 11) & 7;
    int b = i >> 14;
    int wy = n >> 3, wx = n & 7;
    const float* qb = g_qkv + ((size_t)b * 3 * CC + h * DH + d) * HWSZ;
    const float* kb = qb + (size_t)CC * HWSZ;
    float sq = 0.f, sk = 0.f;
    #pragma unroll
    for (int t = 0; t < 16; t++) {
        int hw = ((wy * 4 + (t >> 2)) << 5) + wx * 4 + (t & 3);
        sq += qb[hw];
        sk += kb[hw];
    }
    g_qm[i] = sq * 0.0625f;
    g_km[i] = sk * 0.0625f;
}

// ---------------- affinity + exact top-4 (warp-parallel) ----------------
__global__ void topk_k() {
    int bh = blockIdx.x;                 // b*8 + h
    __shared__ float kt[32][65];
    __shared__ float qs[64][32];
    int tid = threadIdx.x, warp = tid >> 5, lane = tid & 31;
    for (int e = tid; e < 2048; e += 256) {
        int j = e >> 5, d = e & 31;
        kt[d][j] = g_km[(size_t)bh * 2048 + e];
        qs[j][d] = g_qm[(size_t)bh * 2048 + e];
    }
    __syncthreads();
    for (int ii = 0; ii < 8; ii++) {
        int i = warp * 8 + ii;
        float s0 = 0.f, s1 = 0.f;
        #pragma unroll
        for (int d = 0; d < 32; d++) {
            float q = qs[i][d];
            s0 += q * kt[d][lane];
            s1 += q * kt[d][lane + 32];
        }
        float v0 = s0, v1 = s1;
        #pragma unroll
        for (int t = 0; t < KTOP; t++) {
            float bvv; int bj;
            if (v0 >= v1) { bvv = v0; bj = lane; } else { bvv = v1; bj = lane + 32; }
            #pragma unroll
            for (int off = 16; off; off >>= 1) {
                float ov = __shfl_xor_sync(0xffffffffu, bvv, off);
                int   oj = __shfl_xor_sync(0xffffffffu, bj,  off);
                if (ov > bvv || (ov == bvv && oj < bj)) { bvv = ov; bj = oj; }
            }
            if (lane == 0) g_idx[((size_t)bh * 64 + i) * KTOP + t] = bj;
            if (bj == lane)      v0 = -INFINITY;
            if (bj == lane + 32) v1 = -INFINITY;
        }
    }
}

// ---------------- gathered window attention ----------------
__global__ void attn_k() {
    int bid = blockIdx.x;
    int n = bid & 63;
    int h = (bid >> 6) & 7;
    int b = bid >> 9;
    __shared__ float qs[16][33];
    __shared__ float ks[64][33];
    __shared__ float vs[64][33];
    __shared__ float sc[16][64];
    __shared__ int   widx[KTOP];
    int tid = threadIdx.x;
    if (tid < KTOP) widx[tid] = g_idx[(size_t)bid * KTOP + tid];
    __syncthreads();

    int wy = n >> 3, wx = n & 7;
    const float* qbase = g_qkv + ((size_t)b * 3 * CC + h * DH) * HWSZ;
    const float* kbase = qbase + (size_t)CC * HWSZ;
    const float* vbase = qbase + (size_t)2 * CC * HWSZ;

    for (int e = tid; e < 512; e += 128) {
        int d = e >> 4, t = e & 15;
        int hw = ((wy * 4 + (t >> 2)) << 5) + wx * 4 + (t & 3);
        qs[t][d] = qbase[(size_t)d * HWSZ + hw];
    }
    for (int e = tid; e < 2048; e += 128) {
        int d = e >> 6, kt = e & 63;
        int j = widx[kt >> 4];
        int t = kt & 15;
        int jy = j >> 3, jx = j & 7;
        int hw = ((jy * 4 + (t >> 2)) << 5) + jx * 4 + (t & 3);
        ks[kt][d] = kbase[(size_t)d * HWSZ + hw];
        vs[kt][d] = vbase[(size_t)d * HWSZ + hw];
    }
    __syncthreads();

    int warp = tid >> 5, lane = tid & 31;
    const float scale = 0.17677669529663687f;
    #pragma unroll
    for (int rr = 0; rr < 4; rr++) {
        int row = warp * 4 + rr;
        float s0 = 0.f, s1 = 0.f;
        #pragma unroll
        for (int d = 0; d < 32; d++) {
            float qv = qs[row][d];
            s0 += qv * ks[lane][d];
            s1 += qv * ks[lane + 32][d];
        }
        s0 *= scale; s1 *= scale;
        float mx = fmaxf(s0, s1);
        #pragma unroll
        for (int off = 16; off; off >>= 1) mx = fmaxf(mx, __shfl_xor_sync(0xffffffffu, mx, off));
        float e0 = expf(s0 - mx), e1 = expf(s1 - mx);
        float sum = e0 + e1;
        #pragma unroll
        for (int off = 16; off; off >>= 1) sum += __shfl_xor_sync(0xffffffffu, sum, off);
        float inv = 1.0f / sum;
        sc[row][lane]      = e0 * inv;
        sc[row][lane + 32] = e1 * inv;
    }
    __syncwarp();
    float* mbase = g_msg + ((size_t)b * CC + h * DH) * HWSZ;
    #pragma unroll
    for (int rr = 0; rr < 4; rr++) {
        int row = warp * 4 + rr;
        float acc = 0.f;
        #pragma unroll
        for (int k = 0; k < 64; k++) acc += sc[row][k] * vs[k][lane];
        int hw = ((wy * 4 + (row >> 2)) << 5) + wx * 4 + (row & 3);
        mbase[(size_t)lane * HWSZ + hw] = acc;
    }
}

// ---------------- depthwise 3x3 + bn2 + gelu (smem tiled) ----------------
__global__ void dw_k(const float* __restrict__ dw,
                     const float* __restrict__ g2, const float* __restrict__ b2,
                     const float* __restrict__ m2, const float* __restrict__ v2) {
    int bc = blockIdx.x;                  // b*1024 + c
    int c = bc & (MRC - 1);
    __shared__ float t[1024];
    __shared__ float wsh[9];
    int tid = threadIdx.x;
    const float* p = g_h1 + (size_t)bc * HWSZ;
    for (int i = tid; i < 1024; i += 256) t[i] = p[i];
    if (tid < 9) wsh[tid] = dw[c * 9 + tid];
    __syncthreads();
    float s = g2[c] * rsqrtf(v2[c] + EPSV);
    float bs = b2[c] - m2[c] * s;
    float* outp = g_h2 + (size_t)bc * HWSZ;
    #pragma unroll
    for (int it = 0; it < 4; it++) {
        int pix = it * 256 + tid;
        int y = pix >> 5, x = pix & 31;
        float acc = 0.f;
        #pragma unroll
        for (int dy = -1; dy <= 1; dy++) {
            int yy = y + dy;
            if (yy < 0 || yy > 31) continue;
            #pragma unroll
            for (int dx = -1; dx <= 1; dx++) {
                int xx = x + dx;
                if (xx < 0 || xx > 31) continue;
                acc += wsh[(dy + 1) * 3 + (dx + 1)] * t[yy * 32 + xx];
            }
        }
        outp[pix] = gelu_f(acc * s + bs);
    }
}

// ---------------- launcher ----------------
extern "C" void kernel_launch(void* const* d_in, const int* in_sizes, int n_in,
                              void* d_out, int out_size) {
    const float* x      = (const float*)d_in[0];
    const float* bn0_g  = (const float*)d_in[1];
    const float* bn0_b  = (const float*)d_in[2];
    const float* bn0_m  = (const float*)d_in[3];
    const float* bn0_v  = (const float*)d_in[4];
    const float* w_qkv  = (const float*)d_in[5];
    const float* w_mrg  = (const float*)d_in[6];
    const float* b_mrg  = (const float*)d_in[7];
    const float* w1     = (const float*)d_in[8];
    const float* bn1_g  = (const float*)d_in[9];
    const float* bn1_b  = (const float*)d_in[10];
    const float* bn1_m  = (const float*)d_in[11];
    const float* bn1_v  = (const float*)d_in[12];
    const float* dw     = (const float*)d_in[13];
    const float* bn2_g  = (const float*)d_in[14];
    const float* bn2_b  = (const float*)d_in[15];
    const float* bn2_m  = (const float*)d_in[16];
    const float* bn2_v  = (const float*)d_in[17];
    const float* w2     = (const float*)d_in[18];
    const float* bn3_g  = (const float*)d_in[19];
    const float* bn3_b  = (const float*)d_in[20];
    const float* bn3_m  = (const float*)d_in[21];
    const float* bn3_v  = (const float*)d_in[22];

    float *h0, *qkv, *msg, *x1, *h1, *h2;
    cudaGetSymbolAddress((void**)&h0,  g_h0);
    cudaGetSymbolAddress((void**)&qkv, g_qkv);
    cudaGetSymbolAddress((void**)&msg, g_msg);
    cudaGetSymbolAddress((void**)&x1,  g_x1);
    cudaGetSymbolAddress((void**)&h1,  g_h1);
    cudaGetSymbolAddress((void**)&h2,  g_h2);

    cudaFuncSetAttribute(mgemm_k<0>, cudaFuncAttributeMaxDynamicSharedMemorySize, GEMM_SMEM);
    cudaFuncSetAttribute(mgemm_k<1>, cudaFuncAttributeMaxDynamicSharedMemorySize, GEMM_SMEM);
    cudaFuncSetAttribute(mgemm_k<2>, cudaFuncAttributeMaxDynamicSharedMemorySize, GEMM_SMEM);
    cudaFuncSetAttribute(mgemm_k<3>, cudaFuncAttributeMaxDynamicSharedMemorySize, GEMM_SMEM);

    // 1. h0 = gelu(bn0(x))
    bn0_gelu_k<<<(BB * CC * HWSZ + 255) / 256, 256>>>(x, bn0_g, bn0_b, bn0_m, bn0_v);

    // 2. qkv = w_qkv @ h0
    mgemm_k<0><<<dim3(768 / 128, 8, BB), 256, GEMM_SMEM>>>(
        w_qkv, h0, qkv, 768, 256, nullptr, nullptr, nullptr, nullptr, nullptr, nullptr);

    // 3. window means
    wmean_k<<<(BB * HEADS * NWIN * DH + 255) / 256, 256>>>();

    // 4. affinity + top-4
    topk_k<<<BB * HEADS, 256>>>();

    // 5. gathered attention
    attn_k<<<BB * HEADS * NWIN, 128>>>();

    // 6. x1 = x + w_merge @ msg + b_merge
    mgemm_k<1><<<dim3(CC / 128, 8, BB), 256, GEMM_SMEM>>>(
        w_mrg, msg, x1, CC, 256, x, b_mrg, nullptr, nullptr, nullptr, nullptr);

    // 7. h1 = gelu(bn1(w1 @ x1))
    mgemm_k<2><<<dim3(MRC / 128, 8, BB), 256, GEMM_SMEM>>>(
        w1, x1, h1, MRC, 256, nullptr, nullptr, bn1_g, bn1_b, bn1_m, bn1_v);

    // 8. h2 = gelu(bn2(dwconv3x3(h1)))
    dw_k<<<BB * MRC, 256>>>(dw, bn2_g, bn2_b, bn2_m, bn2_v);

    // 9. out = x1 + bn3(w2 @ h2)
    mgemm_k<3><<<dim3(CC / 128, 8, BB), 256, GEMM_SMEM>>>(
        w2, h2, (float*)d_out, CC, 1024, x1, nullptr, bn3_g, bn3_b, bn3_m, bn3_v);
}

// round 4
// speedup vs baseline: 2.6711x; 1.1828x over previous
#include <cuda_runtime.h>
#include <cuda_fp16.h>
#include <cstdint>
#include <math.h>

// ---------------- problem constants ----------------
#define BB   16
#define CC   256
#define HWSZ 1024
#define DH   32
#define HEADS 8
#define KTOP 4
#define MRC  1024
#define NWIN 64
#define EPSV 1e-5f

// ---------------- device scratch ----------------
__device__ float g_h0 [BB * CC  * HWSZ];
__device__ float g_qkv[BB * 3*CC * HWSZ];
__device__ float g_qm [BB * HEADS * NWIN * DH];
__device__ float g_km [BB * HEADS * NWIN * DH];
__device__ int   g_idx[BB * HEADS * NWIN * KTOP];
__device__ float g_msg[BB * CC  * HWSZ];
__device__ float g_x1 [BB * CC  * HWSZ];
__device__ float g_h1 [BB * MRC * HWSZ];
__device__ float g_h2 [BB * MRC * HWSZ];

__device__ __forceinline__ float gelu_f(float x) {
    return 0.5f * x * (1.0f + erff(x * 0.7071067811865475f));
}

// ---------------- fp16 warp MMA ----------------
__device__ __forceinline__ void mma_f16(float* d, const uint32_t* a, uint32_t b0, uint32_t b1) {
    asm volatile(
        "mma.sync.aligned.m16n8k16.row.col.f32.f16.f16.f32 "
        "{%0,%1,%2,%3}, {%4,%5,%6,%7}, {%8,%9}, {%0,%1,%2,%3};"
        : "+f"(d[0]), "+f"(d[1]), "+f"(d[2]), "+f"(d[3])
        : "r"(a[0]), "r"(a[1]), "r"(a[2]), "r"(a[3]), "r"(b0), "r"(b1));
}

__device__ __forceinline__ void cvt_split(float x, __half& h, __half& l) {
    h = __float2half_rn(x);
    l = __float2half_rn(x - __half2float(h));
}

// smem layout constants (per stage)
#define WS_STRIDE 40          // fp16 elems per W row (32 used + pad)
#define AS_STRIDE 34          // fp16 elems per A row (32 used + pad)
#define WS_LO_ELEM 5120       // 128*40
#define AS_BYTE_OFF 20480     // 2*128*40*2
#define AS_LO_ELEM 4352       // 128*34
#define STAGE_BYTES 37888
#define GEMM_SMEM (2 * STAGE_BYTES)

// ---------------- kernel: h0 = gelu(bn0(x)) ----------------
__global__ void bn0_gelu_k(const float* __restrict__ x,
                           const float* __restrict__ g, const float* __restrict__ b,
                           const float* __restrict__ m, const float* __restrict__ v) {
    int i = blockIdx.x * 256 + threadIdx.x;
    if (i >= BB * CC * HWSZ) return;
    int c = (i >> 10) & (CC - 1);
    float s = g[c] * rsqrtf(v[c] + EPSV);
    g_h0[i] = gelu_f((x[i] - m[c]) * s + b[c]);
}

// ---------------- tensor-core fused GEMM (fp16 split) ----------------
// Out[b,o,n] = epilogue( sum_c Wm[o,c] * A[b,c,n] )
// CTA: 128(o) x 128(n), 256 threads = 8 warps (4 in M x 2 in N), warp tile 32x64.
// W always split hi/lo (2 MMA passes). If P3, A also split -> 3rd pass (hi_W*lo_A).
template<int MODE, int P3>
__global__ void __launch_bounds__(256, 1)
mgemm_k(const float* __restrict__ Wm, const float* __restrict__ A,
        float* __restrict__ Out, int O, int Kd,
        const float* __restrict__ Res, const float* __restrict__ bias,
        const float* __restrict__ g,  const float* __restrict__ bb,
        const float* __restrict__ mm, const float* __restrict__ vv) {
    extern __shared__ char smc[];
    const int tid = threadIdx.x, lane = tid & 31, warp = tid >> 5;
    const int b = blockIdx.z, om = blockIdx.x * 128, n0 = blockIdx.y * 128;
    const int wm = warp >> 1, wn = warp & 1;
    const int gq = lane >> 2, tq = lane & 3;

    const float* Wb = Wm + (size_t)om * Kd;
    const float* Ab = A + (size_t)b * Kd * HWSZ + n0;

    float acc[2][8][4];
    #pragma unroll
    for (int mt = 0; mt < 2; mt++)
        #pragma unroll
        for (int nt = 0; nt < 8; nt++)
            #pragma unroll
            for (int r = 0; r < 4; r++) acc[mt][nt][r] = 0.f;

    const int wrow = tid >> 3;
    const int wcol = (tid & 7) * 4;
    const int acr  = tid >> 5;
    const int acn  = (tid & 31) * 4;

    float4 wv[4], av[4];
    const int nch = Kd >> 5;

    #pragma unroll
    for (int it = 0; it < 4; it++)
        wv[it] = *(const float4*)(Wb + (size_t)(it * 32 + wrow) * Kd + wcol);
    #pragma unroll
    for (int it = 0; it < 4; it++)
        av[it] = *(const float4*)(Ab + (size_t)(it * 8 + acr) * HWSZ + acn);

    {
        __half* ws_hi = (__half*)smc;
        __half* ws_lo = ws_hi + WS_LO_ELEM;
        __half* as_hi = (__half*)(smc + AS_BYTE_OFF);
        __half* as_lo = as_hi + AS_LO_ELEM;
        #pragma unroll
        for (int it = 0; it < 4; it++) {
            __half h4[4], l4[4];
            cvt_split(wv[it].x, h4[0], l4[0]); cvt_split(wv[it].y, h4[1], l4[1]);
            cvt_split(wv[it].z, h4[2], l4[2]); cvt_split(wv[it].w, h4[3], l4[3]);
            int idx = (it * 32 + wrow) * WS_STRIDE + wcol;
            *(uint2*)&ws_hi[idx] = *(uint2*)h4;
            *(uint2*)&ws_lo[idx] = *(uint2*)l4;
        }
        #pragma unroll
        for (int it = 0; it < 4; it++) {
            int c = it * 8 + acr;
            float vs4[4] = {av[it].x, av[it].y, av[it].z, av[it].w};
            #pragma unroll
            for (int j = 0; j < 4; j++) {
                __half h, l; cvt_split(vs4[j], h, l);
                as_hi[(acn + j) * AS_STRIDE + c] = h;
                if (P3) as_lo[(acn + j) * AS_STRIDE + c] = l;
            }
        }
    }
    __syncthreads();

    for (int ch = 0; ch < nch; ch++) {
        int s = ch & 1;
        char* st = smc + s * STAGE_BYTES;
        int k0n = (ch + 1) << 5;

        if (ch + 1 < nch) {
            #pragma unroll
            for (int it = 0; it < 4; it++)
                wv[it] = *(const float4*)(Wb + (size_t)(it * 32 + wrow) * Kd + k0n + wcol);
            #pragma unroll
            for (int it = 0; it < 4; it++)
                av[it] = *(const float4*)(Ab + (size_t)(k0n + it * 8 + acr) * HWSZ + acn);
        }

        const __half* ws_hi = (const __half*)st;
        const __half* ws_lo = ws_hi + WS_LO_ELEM;
        const __half* as_hi = (const __half*)(st + AS_BYTE_OFF);
        const __half* as_lo = as_hi + AS_LO_ELEM;

        #pragma unroll
        for (int ks = 0; ks < 2; ks++) {
            uint32_t afh[2][4], afl[2][4];
            #pragma unroll
            for (int mt = 0; mt < 2; mt++) {
                int rb = wm * 32 + mt * 16;
                int cb = ks * 16 + 2 * tq;
                afh[mt][0] = *(const uint32_t*)&ws_hi[(rb + gq)     * WS_STRIDE + cb];
                afh[mt][1] = *(const uint32_t*)&ws_hi[(rb + gq + 8) * WS_STRIDE + cb];
                afh[mt][2] = *(const uint32_t*)&ws_hi[(rb + gq)     * WS_STRIDE + cb + 8];
                afh[mt][3] = *(const uint32_t*)&ws_hi[(rb + gq + 8) * WS_STRIDE + cb + 8];
                afl[mt][0] = *(const uint32_t*)&ws_lo[(rb + gq)     * WS_STRIDE + cb];
                afl[mt][1] = *(const uint32_t*)&ws_lo[(rb + gq + 8) * WS_STRIDE + cb];
                afl[mt][2] = *(const uint32_t*)&ws_lo[(rb + gq)     * WS_STRIDE + cb + 8];
                afl[mt][3] = *(const uint32_t*)&ws_lo[(rb + gq + 8) * WS_STRIDE + cb + 8];
            }
            #pragma unroll
            for (int nt = 0; nt < 8; nt++) {
                int nb = wn * 64 + nt * 8 + gq;
                int kb = ks * 16 + 2 * tq;
                uint32_t bh0 = *(const uint32_t*)&as_hi[nb * AS_STRIDE + kb];
                uint32_t bh1 = *(const uint32_t*)&as_hi[nb * AS_STRIDE + kb + 8];
                #pragma unroll
                for (int mt = 0; mt < 2; mt++) {
                    mma_f16(acc[mt][nt], afh[mt], bh0, bh1);
                    mma_f16(acc[mt][nt], afl[mt], bh0, bh1);
                }
                if (P3) {
                    uint32_t bl0 = *(const uint32_t*)&as_lo[nb * AS_STRIDE + kb];
                    uint32_t bl1 = *(const uint32_t*)&as_lo[nb * AS_STRIDE + kb + 8];
                    #pragma unroll
                    for (int mt = 0; mt < 2; mt++)
                        mma_f16(acc[mt][nt], afh[mt], bl0, bl1);
                }
            }
        }

        if (ch + 1 < nch) {
            char* st2 = smc + (s ^ 1) * STAGE_BYTES;
            __half* ws_hi2 = (__half*)st2;
            __half* ws_lo2 = ws_hi2 + WS_LO_ELEM;
            __half* as_hi2 = (__half*)(st2 + AS_BYTE_OFF);
            __half* as_lo2 = as_hi2 + AS_LO_ELEM;
            #pragma unroll
            for (int it = 0; it < 4; it++) {
                __half h4[4], l4[4];
                cvt_split(wv[it].x, h4[0], l4[0]); cvt_split(wv[it].y, h4[1], l4[1]);
                cvt_split(wv[it].z, h4[2], l4[2]); cvt_split(wv[it].w, h4[3], l4[3]);
                int idx = (it * 32 + wrow) * WS_STRIDE + wcol;
                *(uint2*)&ws_hi2[idx] = *(uint2*)h4;
                *(uint2*)&ws_lo2[idx] = *(uint2*)l4;
            }
            #pragma unroll
            for (int it = 0; it < 4; it++) {
                int c = it * 8 + acr;
                float vs4[4] = {av[it].x, av[it].y, av[it].z, av[it].w};
                #pragma unroll
                for (int j = 0; j < 4; j++) {
                    __half h, l; cvt_split(vs4[j], h, l);
                    as_hi2[(acn + j) * AS_STRIDE + c] = h;
                    if (P3) as_lo2[(acn + j) * AS_STRIDE + c] = l;
                }
            }
        }
        __syncthreads();
    }

    // ---- epilogue ----
    #pragma unroll
    for (int mt = 0; mt < 2; mt++) {
        int o0 = om + wm * 32 + mt * 16 + gq;
        int o1 = o0 + 8;
        float s0 = 0.f, bs0 = 0.f, s1 = 0.f, bs1 = 0.f, bi0 = 0.f, bi1 = 0.f;
        if (MODE == 2 || MODE == 3) {
            s0 = g[o0] * rsqrtf(vv[o0] + EPSV); bs0 = bb[o0] - mm[o0] * s0;
            s1 = g[o1] * rsqrtf(vv[o1] + EPSV); bs1 = bb[o1] - mm[o1] * s1;
        }
        if (MODE == 1) { bi0 = bias[o0]; bi1 = bias[o1]; }
        #pragma unroll
        for (int nt = 0; nt < 8; nt++) {
            int n = n0 + wn * 64 + nt * 8 + 2 * tq;
            size_t oi0 = ((size_t)b * O + o0) * HWSZ + n;
            size_t oi1 = ((size_t)b * O + o1) * HWSZ + n;
            float r0 = acc[mt][nt][0], r1 = acc[mt][nt][1];
            float r2 = acc[mt][nt][2], r3 = acc[mt][nt][3];
            if (MODE == 1) {
                float2 e0 = *(const float2*)&Res[oi0];
                float2 e1 = *(const float2*)&Res[oi1];
                r0 += e0.x + bi0; r1 += e0.y + bi0;
                r2 += e1.x + bi1; r3 += e1.y + bi1;
            }
            if (MODE == 2) {
                r0 = gelu_f(r0 * s0 + bs0); r1 = gelu_f(r1 * s0 + bs0);
                r2 = gelu_f(r2 * s1 + bs1); r3 = gelu_f(r3 * s1 + bs1);
            }
            if (MODE == 3) {
                float2 e0 = *(const float2*)&Res[oi0];
                float2 e1 = *(const float2*)&Res[oi1];
                r0 = e0.x + r0 * s0 + bs0; r1 = e0.y + r1 * s0 + bs0;
                r2 = e1.x + r2 * s1 + bs1; r3 = e1.y + r3 * s1 + bs1;
            }
            float2 v0 = {r0, r1}, v1 = {r2, r3};
            *(float2*)&Out[oi0] = v0;
            *(float2*)&Out[oi1] = v1;
        }
    }
}

// ---------------- window means (coalesced): block per (b,h) ----------------
__global__ void wmean_k() {
    int bh = blockIdx.x;                 // b*8 + h
    int b = bh >> 3, h = bh & 7;
    int tid = threadIdx.x;
    __shared__ float spq[256], spk[256];
    const float* qpl = g_qkv + ((size_t)b * 3 * CC + h * DH) * HWSZ;
    const float* kpl = qpl + (size_t)CC * HWSZ;
    // thread tid: float4 at pix=tid*4 -> window w = (tid>>5)*8 + (tid&7)
    int w = (tid >> 5) * 8 + (tid & 7);
    for (int d = 0; d < DH; d++) {
        float4 vq = ((const float4*)(qpl + (size_t)d * HWSZ))[tid];
        float4 vk = ((const float4*)(kpl + (size_t)d * HWSZ))[tid];
        spq[tid] = vq.x + vq.y + vq.z + vq.w;
        spk[tid] = vk.x + vk.y + vk.z + vk.w;
        __syncthreads();
        if (tid < 64) {
            int wy = tid >> 3, wx = tid & 7;
            int base = wy * 32 + wx;
            float sq = spq[base] + spq[base + 8] + spq[base + 16] + spq[base + 24];
            float sk = spk[base] + spk[base + 8] + spk[base + 16] + spk[base + 24];
            g_qm[((size_t)bh * 64 + tid) * DH + d] = sq * 0.0625f;
            g_km[((size_t)bh * 64 + tid) * DH + d] = sk * 0.0625f;
        }
        __syncthreads();
    }
    (void)w;
}

// ---------------- affinity + exact top-4 (warp-parallel) ----------------
__global__ void topk_k() {
    int bh = blockIdx.x;
    __shared__ float kt[32][65];
    __shared__ float qs[64][32];
    int tid = threadIdx.x, warp = tid >> 5, lane = tid & 31;
    for (int e = tid; e < 2048; e += 256) {
        int j = e >> 5, d = e & 31;
        kt[d][j] = g_km[(size_t)bh * 2048 + e];
        qs[j][d] = g_qm[(size_t)bh * 2048 + e];
    }
    __syncthreads();
    for (int ii = 0; ii < 8; ii++) {
        int i = warp * 8 + ii;
        float s0 = 0.f, s1 = 0.f;
        #pragma unroll
        for (int d = 0; d < 32; d++) {
            float q = qs[i][d];
            s0 += q * kt[d][lane];
            s1 += q * kt[d][lane + 32];
        }
        float v0 = s0, v1 = s1;
        #pragma unroll
        for (int t = 0; t < KTOP; t++) {
            float bvv; int bj;
            if (v0 >= v1) { bvv = v0; bj = lane; } else { bvv = v1; bj = lane + 32; }
            #pragma unroll
            for (int off = 16; off; off >>= 1) {
                float ov = __shfl_xor_sync(0xffffffffu, bvv, off);
                int   oj = __shfl_xor_sync(0xffffffffu, bj,  off);
                if (ov > bvv || (ov == bvv && oj < bj)) { bvv = ov; bj = oj; }
            }
            if (lane == 0) g_idx[((size_t)bh * 64 + i) * KTOP + t] = bj;
            if (bj == lane)      v0 = -INFINITY;
            if (bj == lane + 32) v1 = -INFINITY;
        }
    }
}

// ---------------- gathered window attention ----------------
__global__ void attn_k() {
    int bid = blockIdx.x;
    int n = bid & 63;
    int h = (bid >> 6) & 7;
    int b = bid >> 9;
    __shared__ float qs[16][33];
    __shared__ float ks[64][33];
    __shared__ float vs[64][33];
    __shared__ float sc[16][64];
    __shared__ int   widx[KTOP];
    int tid = threadIdx.x;
    if (tid < KTOP) widx[tid] = g_idx[(size_t)bid * KTOP + tid];
    __syncthreads();

    int wy = n >> 3, wx = n & 7;
    const float* qbase = g_qkv + ((size_t)b * 3 * CC + h * DH) * HWSZ;
    const float* kbase = qbase + (size_t)CC * HWSZ;
    const float* vbase = qbase + (size_t)2 * CC * HWSZ;

    for (int e = tid; e < 512; e += 128) {
        int d = e >> 4, t = e & 15;
        int hw = ((wy * 4 + (t >> 2)) << 5) + wx * 4 + (t & 3);
        qs[t][d] = qbase[(size_t)d * HWSZ + hw];
    }
    for (int e = tid; e < 2048; e += 128) {
        int d = e >> 6, kt = e & 63;
        int j = widx[kt >> 4];
        int t = kt & 15;
        int jy = j >> 3, jx = j & 7;
        int hw = ((jy * 4 + (t >> 2)) << 5) + jx * 4 + (t & 3);
        ks[kt][d] = kbase[(size_t)d * HWSZ + hw];
        vs[kt][d] = vbase[(size_t)d * HWSZ + hw];
    }
    __syncthreads();

    int warp = tid >> 5, lane = tid & 31;
    const float scale = 0.17677669529663687f;
    #pragma unroll
    for (int rr = 0; rr < 4; rr++) {
        int row = warp * 4 + rr;
        float s0 = 0.f, s1 = 0.f;
        #pragma unroll
        for (int d = 0; d < 32; d++) {
            float qv = qs[row][d];
            s0 += qv * ks[lane][d];
            s1 += qv * ks[lane + 32][d];
        }
        s0 *= scale; s1 *= scale;
        float mx = fmaxf(s0, s1);
        #pragma unroll
        for (int off = 16; off; off >>= 1) mx = fmaxf(mx, __shfl_xor_sync(0xffffffffu, mx, off));
        float e0 = expf(s0 - mx), e1 = expf(s1 - mx);
        float sum = e0 + e1;
        #pragma unroll
        for (int off = 16; off; off >>= 1) sum += __shfl_xor_sync(0xffffffffu, sum, off);
        float inv = 1.0f / sum;
        sc[row][lane]      = e0 * inv;
        sc[row][lane + 32] = e1 * inv;
    }
    __syncwarp();
    float* mbase = g_msg + ((size_t)b * CC + h * DH) * HWSZ;
    #pragma unroll
    for (int rr = 0; rr < 4; rr++) {
        int row = warp * 4 + rr;
        float acc = 0.f;
        #pragma unroll
        for (int k = 0; k < 64; k++) acc += sc[row][k] * vs[k][lane];
        int hw = ((wy * 4 + (row >> 2)) << 5) + wx * 4 + (row & 3);
        mbase[(size_t)lane * HWSZ + hw] = acc;
    }
}

// ---------------- depthwise 3x3 + bn2 + gelu (smem tiled) ----------------
__global__ void dw_k(const float* __restrict__ dw,
                     const float* __restrict__ g2, const float* __restrict__ b2,
                     const float* __restrict__ m2, const float* __restrict__ v2) {
    int bc = blockIdx.x;
    int c = bc & (MRC - 1);
    __shared__ float t[1024];
    __shared__ float wsh[9];
    int tid = threadIdx.x;
    const float* p = g_h1 + (size_t)bc * HWSZ;
    for (int i = tid; i < 1024; i += 256) t[i] = p[i];
    if (tid < 9) wsh[tid] = dw[c * 9 + tid];
    __syncthreads();
    float s = g2[c] * rsqrtf(v2[c] + EPSV);
    float bs = b2[c] - m2[c] * s;
    float* outp = g_h2 + (size_t)bc * HWSZ;
    #pragma unroll
    for (int it = 0; it < 4; it++) {
        int pix = it * 256 + tid;
        int y = pix >> 5, x = pix & 31;
        float acc = 0.f;
        #pragma unroll
        for (int dy = -1; dy <= 1; dy++) {
            int yy = y + dy;
            if (yy < 0 || yy > 31) continue;
            #pragma unroll
            for (int dx = -1; dx <= 1; dx++) {
                int xx = x + dx;
                if (xx < 0 || xx > 31) continue;
                acc += wsh[(dy + 1) * 3 + (dx + 1)] * t[yy * 32 + xx];
            }
        }
        outp[pix] = gelu_f(acc * s + bs);
    }
}

// ---------------- launcher ----------------
extern "C" void kernel_launch(void* const* d_in, const int* in_sizes, int n_in,
                              void* d_out, int out_size) {
    const float* x      = (const float*)d_in[0];
    const float* bn0_g  = (const float*)d_in[1];
    const float* bn0_b  = (const float*)d_in[2];
    const float* bn0_m  = (const float*)d_in[3];
    const float* bn0_v  = (const float*)d_in[4];
    const float* w_qkv  = (const float*)d_in[5];
    const float* w_mrg  = (const float*)d_in[6];
    const float* b_mrg  = (const float*)d_in[7];
    const float* w1     = (const float*)d_in[8];
    const float* bn1_g  = (const float*)d_in[9];
    const float* bn1_b  = (const float*)d_in[10];
    const float* bn1_m  = (const float*)d_in[11];
    const float* bn1_v  = (const float*)d_in[12];
    const float* dw     = (const float*)d_in[13];
    const float* bn2_g  = (const float*)d_in[14];
    const float* bn2_b  = (const float*)d_in[15];
    const float* bn2_m  = (const float*)d_in[16];
    const float* bn2_v  = (const float*)d_in[17];
    const float* w2     = (const float*)d_in[18];
    const float* bn3_g  = (const float*)d_in[19];
    const float* bn3_b  = (const float*)d_in[20];
    const float* bn3_m  = (const float*)d_in[21];
    const float* bn3_v  = (const float*)d_in[22];

    float *h0, *qkv, *msg, *x1, *h1, *h2;
    cudaGetSymbolAddress((void**)&h0,  g_h0);
    cudaGetSymbolAddress((void**)&qkv, g_qkv);
    cudaGetSymbolAddress((void**)&msg, g_msg);
    cudaGetSymbolAddress((void**)&x1,  g_x1);
    cudaGetSymbolAddress((void**)&h1,  g_h1);
    cudaGetSymbolAddress((void**)&h2,  g_h2);

    cudaFuncSetAttribute((const void*)mgemm_k<0,1>, cudaFuncAttributeMaxDynamicSharedMemorySize, GEMM_SMEM);
    cudaFuncSetAttribute((const void*)mgemm_k<1,0>, cudaFuncAttributeMaxDynamicSharedMemorySize, GEMM_SMEM);
    cudaFuncSetAttribute((const void*)mgemm_k<2,0>, cudaFuncAttributeMaxDynamicSharedMemorySize, GEMM_SMEM);
    cudaFuncSetAttribute((const void*)mgemm_k<3,0>, cudaFuncAttributeMaxDynamicSharedMemorySize, GEMM_SMEM);

    // 1. h0 = gelu(bn0(x))
    bn0_gelu_k<<<(BB * CC * HWSZ + 255) / 256, 256>>>(x, bn0_g, bn0_b, bn0_m, bn0_v);

    // 2. qkv = w_qkv @ h0   (3-pass: protects top-k selection accuracy)
    mgemm_k<0,1><<<dim3(768 / 128, 8, BB), 256, GEMM_SMEM>>>(
        w_qkv, h0, qkv, 768, 256, nullptr, nullptr, nullptr, nullptr, nullptr, nullptr);

    // 3. window means (coalesced)
    wmean_k<<<BB * HEADS, 256>>>();

    // 4. affinity + top-4
    topk_k<<<BB * HEADS, 256>>>();

    // 5. gathered attention
    attn_k<<<BB * HEADS * NWIN, 128>>>();

    // 6. x1 = x + w_merge @ msg + b_merge
    mgemm_k<1,0><<<dim3(CC / 128, 8, BB), 256, GEMM_SMEM>>>(
        w_mrg, msg, x1, CC, 256, x, b_mrg, nullptr, nullptr, nullptr, nullptr);

    // 7. h1 = gelu(bn1(w1 @ x1))
    mgemm_k<2,0><<<dim3(MRC / 128, 8, BB), 256, GEMM_SMEM>>>(
        w1, x1, h1, MRC, 256, nullptr, nullptr, bn1_g, bn1_b, bn1_m, bn1_v);

    // 8. h2 = gelu(bn2(dwconv3x3(h1)))
    dw_k<<<BB * MRC, 256>>>(dw, bn2_g, bn2_b, bn2_m, bn2_v);

    // 9. out = x1 + bn3(w2 @ h2)
    mgemm_k<3,0><<<dim3(CC / 128, 8, BB), 256, GEMM_SMEM>>>(
        w2, h2, (float*)d_out, CC, 1024, x1, nullptr, bn3_g, bn3_b, bn3_m, bn3_v);
}